// round 1
// baseline (speedup 1.0000x reference)
#include <cuda_runtime.h>
#include <math.h>

// ---------------------------------------------------------------- constants
#define D_MODEL 512
#define D_INNER 512
#define D_STATE 16
#define DT_RANK 32
#define BB      4
#define LL      2048
#define MTOK    (BB*LL)       // 8192 tokens
#define CH_T    64            // scan chunk length
#define NCHUNK  (LL/CH_T)     // 32 chunks

// ---------------------------------------------------------------- scratch
__device__ __align__(16) float g_hstats[BB*D_MODEL];
__device__ __align__(16) float g_h    [MTOK*D_MODEL];
__device__ __align__(16) float g_xn   [MTOK*D_MODEL];
__device__ __align__(16) float g_xz   [MTOK*2*D_INNER];
__device__ __align__(16) float g_u    [MTOK*D_INNER];
__device__ __align__(16) float g_xdbc [MTOK*64];
__device__ __align__(16) float g_delta[MTOK*D_INNER];
__device__ __align__(16) float g_q    [BB*D_INNER*NCHUNK*D_STATE];
__device__ __align__(16) float g_dsum [BB*D_INNER*NCHUNK];
__device__ __align__(16) float g_hinit[BB*D_INNER*NCHUNK*D_STATE];
__device__ __align__(16) float g_y    [MTOK*D_INNER];

// ---------------------------------------------------------------- SGEMM (NT)
// C[M,N] = A[M,K] @ B[N,K]^T  (both operands K-contiguous, row-major)
// EPI: 0 = none, 1 = relu(acc + bias[(m/L)*512 + n]), 2 = softplus(acc + bias[n])
template<int BM, int BN, int TM, int TN, int EPI>
__global__ __launch_bounds__(256)
void sgemm_nt(const float* __restrict__ A, const float* __restrict__ B,
              float* __restrict__ C, int M, int N, int K,
              int lda, int ldb, int ldc, const float* __restrict__ bias)
{
    constexpr int BK = 16;
    __shared__ float As[BK][BM + 4];
    __shared__ float Bs[BK][BN + 4];

    const int tid = threadIdx.x;
    const int tx  = tid & 15;
    const int ty  = tid >> 4;
    const int m0  = blockIdx.y * BM;
    const int n0  = blockIdx.x * BN;

    float acc[TM][TN];
#pragma unroll
    for (int i = 0; i < TM; i++)
#pragma unroll
        for (int j = 0; j < TN; j++) acc[i][j] = 0.f;

    const float* Ab = A + (size_t)m0 * lda;
    const float* Bb = B + (size_t)n0 * ldb;

    for (int k0 = 0; k0 < K; k0 += BK) {
        // load A tile (transposed into smem):   BM rows x BK cols
#pragma unroll
        for (int i = 0; i < (BM * BK) / 1024; i++) {
            int t = tid + i * 256;
            int r = t >> 2, cq = t & 3;
            float4 v = *(const float4*)(Ab + (size_t)r * lda + k0 + cq * 4);
            As[cq*4+0][r] = v.x; As[cq*4+1][r] = v.y;
            As[cq*4+2][r] = v.z; As[cq*4+3][r] = v.w;
        }
        // load B tile (transposed into smem):   BN rows x BK cols
#pragma unroll
        for (int i = 0; i < (BN * BK) / 1024; i++) {
            int t = tid + i * 256;
            int r = t >> 2, cq = t & 3;
            float4 v = *(const float4*)(Bb + (size_t)r * ldb + k0 + cq * 4);
            Bs[cq*4+0][r] = v.x; Bs[cq*4+1][r] = v.y;
            Bs[cq*4+2][r] = v.z; Bs[cq*4+3][r] = v.w;
        }
        __syncthreads();

#pragma unroll
        for (int k = 0; k < BK; k++) {
            float a[TM], b[TN];
#pragma unroll
            for (int i = 0; i < TM; i += 4) {
                float4 v = *(const float4*)&As[k][ty * TM + i];
                a[i] = v.x; a[i+1] = v.y; a[i+2] = v.z; a[i+3] = v.w;
            }
#pragma unroll
            for (int j = 0; j < TN; j += 4) {
                float4 v = *(const float4*)&Bs[k][tx * TN + j];
                b[j] = v.x; b[j+1] = v.y; b[j+2] = v.z; b[j+3] = v.w;
            }
#pragma unroll
            for (int i = 0; i < TM; i++)
#pragma unroll
                for (int j = 0; j < TN; j++)
                    acc[i][j] = fmaf(a[i], b[j], acc[i][j]);
        }
        __syncthreads();
    }

#pragma unroll
    for (int i = 0; i < TM; i++) {
        int m = m0 + ty * TM + i;
#pragma unroll
        for (int j = 0; j < TN; j++) {
            int n = n0 + tx * TN + j;
            float v = acc[i][j];
            if (EPI == 1) {                 // gate MLP: + hstats[batch], relu
                v += bias[(m >> 11) * D_MODEL + n];   // m/2048 = batch
                v = fmaxf(v, 0.f);
            } else if (EPI == 2) {          // dt_proj: + bias, softplus
                v += bias[n];
                v = (v > 20.f) ? v : log1pf(expf(v));
            }
            C[(size_t)m * ldc + n] = v;
        }
    }
}

// ---------------------------------------------------------------- hstats
// hstats[b][j] = gb1[j] + sum_k gW1[j, 512+k] * x_stats[b,k]
__global__ void hstats_kernel(const float* __restrict__ gW1,
                              const float* __restrict__ gb1,
                              const float* __restrict__ xstat)
{
    int idx = blockIdx.x * blockDim.x + threadIdx.x;
    if (idx >= BB * D_MODEL) return;
    int b = idx >> 9, j = idx & 511;
    const float* w  = gW1 + (size_t)j * (2 * D_MODEL) + D_MODEL;
    const float* xs = xstat + b * D_MODEL;
    float s = gb1[j];
#pragma unroll 8
    for (int k = 0; k < D_MODEL; k++) s = fmaf(w[k], xs[k], s);
    g_hstats[idx] = s;
}

// ---------------------------------------------------------------- gate + LN
__global__ __launch_bounds__(256)
void gate_ln_kernel(const float* __restrict__ xsig, const float* __restrict__ xstat,
                    const float* __restrict__ h,    const float* __restrict__ gW2,
                    const float* __restrict__ gb2,  const float* __restrict__ lng,
                    const float* __restrict__ lnb,  float* __restrict__ xn)
{
    const int t = blockIdx.x;          // token
    const int b = t >> 11;             // t / 2048
    const int tid = threadIdx.x;
    const int d0 = tid, d1 = tid + 256;

    __shared__ float sred[8];
    __shared__ float sred2[8][2];
    __shared__ float sbc[2];

    const float* hr = h + (size_t)t * D_MODEL;
    float p = hr[d0] * gW2[d0] + hr[d1] * gW2[d1];
#pragma unroll
    for (int o = 16; o > 0; o >>= 1) p += __shfl_xor_sync(0xffffffffu, p, o);
    if ((tid & 31) == 0) sred[tid >> 5] = p;
    __syncthreads();
    if (tid == 0) {
        float s = 0.f;
        for (int w = 0; w < 8; w++) s += sred[w];
        sbc[0] = 1.f / (1.f + expf(-(s + gb2[0])));
    }
    __syncthreads();
    const float gate = sbc[0];

    float x0 = xsig[(size_t)t * D_MODEL + d0] + gate * xstat[b * D_MODEL + d0];
    float x1 = xsig[(size_t)t * D_MODEL + d1] + gate * xstat[b * D_MODEL + d1];
    float s  = x0 + x1;
    float ss = x0 * x0 + x1 * x1;
#pragma unroll
    for (int o = 16; o > 0; o >>= 1) {
        s  += __shfl_xor_sync(0xffffffffu, s,  o);
        ss += __shfl_xor_sync(0xffffffffu, ss, o);
    }
    if ((tid & 31) == 0) { sred2[tid >> 5][0] = s; sred2[tid >> 5][1] = ss; }
    __syncthreads();
    if (tid == 0) {
        float S = 0.f, SS = 0.f;
        for (int w = 0; w < 8; w++) { S += sred2[w][0]; SS += sred2[w][1]; }
        float mu  = S * (1.f / D_MODEL);
        float var = SS * (1.f / D_MODEL) - mu * mu;
        sbc[0] = mu;
        sbc[1] = rsqrtf(var + 1e-5f);
    }
    __syncthreads();
    const float mu = sbc[0], rstd = sbc[1];
    xn[(size_t)t * D_MODEL + d0] = (x0 - mu) * rstd * lng[d0] + lnb[d0];
    xn[(size_t)t * D_MODEL + d1] = (x1 - mu) * rstd * lng[d1] + lnb[d1];
}

// ---------------------------------------------------------------- conv(k=2)+silu
__global__ void conv_silu_kernel(const float* __restrict__ xz,
                                 const float* __restrict__ conv_w,
                                 const float* __restrict__ conv_b,
                                 float* __restrict__ u)
{
    int idx = blockIdx.x * blockDim.x + threadIdx.x;
    if (idx >= MTOK * D_INNER) return;
    int d = idx & 511;
    int l = (idx >> 9) & (LL - 1);
    int t = idx >> 9;                                  // b*L + l
    float ucur  = xz[(size_t)t * (2 * D_INNER) + d];
    float uprev = (l > 0) ? xz[(size_t)(t - 1) * (2 * D_INNER) + d] : 0.f;
    float v = conv_b[d] + conv_w[d * 2 + 0] * uprev + conv_w[d * 2 + 1] * ucur;
    float sg = 1.f / (1.f + __expf(-v));
    u[idx] = v * sg;
}

// ---------------------------------------------------------------- scan helpers
__device__ __forceinline__ bool load_aexp(const float* __restrict__ A_log,
                                          int d, float* aexp)
{
    bool fast = true;
#pragma unroll
    for (int n = 0; n < D_STATE; n++) {
        aexp[n] = expf(A_log[d * D_STATE + n]);        // = -A[d,n]
        if (fabsf(aexp[n] - (float)(n + 1)) > 1e-2f) fast = false;
    }
    return fast;
}

// ---- pass 1: per-chunk local scan (h starts at 0) -> q[16], sum(delta)
__global__ __launch_bounds__(128)
void scan_c1(const float* __restrict__ xdbc, const float* __restrict__ delta,
             const float* __restrict__ u,    const float* __restrict__ A_log)
{
    const int d = blockIdx.x * 128 + threadIdx.x;
    const int c = blockIdx.y, b = blockIdx.z;

    __shared__ float sB[CH_T * D_STATE];
    for (int i = threadIdx.x; i < CH_T * D_STATE; i += 128) {
        int j = i >> 4, n = i & 15;
        sB[i] = xdbc[(size_t)(b * LL + c * CH_T + j) * 64 + DT_RANK + n];
    }
    __syncthreads();

    float aexp[D_STATE];
    const bool fast = load_aexp(A_log, d, aexp);

    float h[D_STATE];
#pragma unroll
    for (int n = 0; n < D_STATE; n++) h[n] = 0.f;
    float dsum = 0.f;

    const float* dp = delta + (size_t)(b * LL + c * CH_T) * D_INNER + d;
    const float* up = u     + (size_t)(b * LL + c * CH_T) * D_INNER + d;

    if (fast) {
        for (int j = 0; j < CH_T; j++) {
            float de = dp[j * D_INNER], uu = up[j * D_INNER];
            dsum += de;
            float du = de * uu;
            float r = __expf(-de), rp = r;
#pragma unroll
            for (int n = 0; n < D_STATE; n++) {
                h[n] = fmaf(rp, h[n], du * sB[j * D_STATE + n]);
                rp *= r;
            }
        }
    } else {
        for (int j = 0; j < CH_T; j++) {
            float de = dp[j * D_INNER], uu = up[j * D_INNER];
            dsum += de;
            float du = de * uu;
#pragma unroll
            for (int n = 0; n < D_STATE; n++)
                h[n] = fmaf(__expf(-de * aexp[n]), h[n], du * sB[j * D_STATE + n]);
        }
    }

    const size_t base = (size_t)(b * D_INNER + d) * NCHUNK + c;
#pragma unroll
    for (int n = 0; n < D_STATE; n++) g_q[base * D_STATE + n] = h[n];
    g_dsum[base] = dsum;
}

// ---- pass 2: cross-chunk scan (per (b,d)) -> hinit per chunk
__global__ void scan_c2(const float* __restrict__ A_log)
{
    int bd = blockIdx.x * blockDim.x + threadIdx.x;
    if (bd >= BB * D_INNER) return;
    int d = bd & 511;

    float aexp[D_STATE];
    const bool fast = load_aexp(A_log, d, aexp);

    float h[D_STATE];
#pragma unroll
    for (int n = 0; n < D_STATE; n++) h[n] = 0.f;

    for (int c = 0; c < NCHUNK; c++) {
        const size_t base = (size_t)bd * NCHUNK + c;
#pragma unroll
        for (int n = 0; n < D_STATE; n++) g_hinit[base * D_STATE + n] = h[n];
        float ds = g_dsum[base];
        if (fast) {
            float r = __expf(-ds), rp = r;
#pragma unroll
            for (int n = 0; n < D_STATE; n++) {
                h[n] = fmaf(rp, h[n], g_q[base * D_STATE + n]);
                rp *= r;
            }
        } else {
#pragma unroll
            for (int n = 0; n < D_STATE; n++)
                h[n] = fmaf(__expf(-ds * aexp[n]), h[n], g_q[base * D_STATE + n]);
        }
    }
}

// ---- pass 3: per-chunk replay with correct init; y = <h,C>, fused epilogue
__global__ __launch_bounds__(128)
void scan_c3(const float* __restrict__ xdbc, const float* __restrict__ delta,
             const float* __restrict__ u,    const float* __restrict__ A_log,
             const float* __restrict__ Dp,   const float* __restrict__ xz,
             float* __restrict__ y)
{
    const int d = blockIdx.x * 128 + threadIdx.x;
    const int c = blockIdx.y, b = blockIdx.z;

    __shared__ float sB[CH_T * D_STATE];
    __shared__ float sC[CH_T * D_STATE];
    for (int i = threadIdx.x; i < CH_T * D_STATE; i += 128) {
        int j = i >> 4, n = i & 15;
        const float* row = xdbc + (size_t)(b * LL + c * CH_T + j) * 64;
        sB[i] = row[DT_RANK + n];
        sC[i] = row[DT_RANK + D_STATE + n];
    }
    __syncthreads();

    float aexp[D_STATE];
    const bool fast = load_aexp(A_log, d, aexp);

    const size_t base = (size_t)(b * D_INNER + d) * NCHUNK + c;
    float h[D_STATE];
#pragma unroll
    for (int n = 0; n < D_STATE; n++) h[n] = g_hinit[base * D_STATE + n];

    const float dpd = Dp[d];
    const float* dptr = delta + (size_t)(b * LL + c * CH_T) * D_INNER + d;
    const float* uptr = u     + (size_t)(b * LL + c * CH_T) * D_INNER + d;

    for (int j = 0; j < CH_T; j++) {
        float de = dptr[j * D_INNER], uu = uptr[j * D_INNER];
        float du = de * uu;
        float yv = 0.f;
        if (fast) {
            float r = __expf(-de), rp = r;
#pragma unroll
            for (int n = 0; n < D_STATE; n++) {
                h[n] = fmaf(rp, h[n], du * sB[j * D_STATE + n]);
                yv   = fmaf(h[n], sC[j * D_STATE + n], yv);
                rp *= r;
            }
        } else {
#pragma unroll
            for (int n = 0; n < D_STATE; n++) {
                h[n] = fmaf(__expf(-de * aexp[n]), h[n], du * sB[j * D_STATE + n]);
                yv   = fmaf(h[n], sC[j * D_STATE + n], yv);
            }
        }
        const int l = b * LL + c * CH_T + j;
        float z  = xz[(size_t)l * (2 * D_INNER) + D_INNER + d];
        float sg = 1.f / (1.f + __expf(-z));
        y[(size_t)l * D_INNER + d] = (yv + dpd * uu) * (z * sg);
    }
}

// ---------------------------------------------------------------- launch
static float* symaddr(const void* sym)
{
    void* p = nullptr;
    cudaGetSymbolAddress(&p, sym);
    return (float*)p;
}

extern "C" void kernel_launch(void* const* d_in, const int* in_sizes, int n_in,
                              void* d_out, int out_size)
{
    const float* x_signal  = (const float*)d_in[0];
    const float* x_stats   = (const float*)d_in[1];
    const float* gW1       = (const float*)d_in[2];
    const float* gb1       = (const float*)d_in[3];
    const float* gW2       = (const float*)d_in[4];
    const float* gb2       = (const float*)d_in[5];
    const float* ln_g      = (const float*)d_in[6];
    const float* ln_b      = (const float*)d_in[7];
    const float* in_proj_W = (const float*)d_in[8];
    const float* conv_w    = (const float*)d_in[9];
    const float* conv_b    = (const float*)d_in[10];
    const float* x_proj_W  = (const float*)d_in[11];
    const float* dt_proj_W = (const float*)d_in[12];
    const float* dt_proj_b = (const float*)d_in[13];
    const float* A_log     = (const float*)d_in[14];
    const float* Dp        = (const float*)d_in[15];
    const float* out_proj_W= (const float*)d_in[16];
    float* out = (float*)d_out;

    float* p_hstats = symaddr(g_hstats);
    float* p_h      = symaddr(g_h);
    float* p_xn     = symaddr(g_xn);
    float* p_xz     = symaddr(g_xz);
    float* p_u      = symaddr(g_u);
    float* p_xdbc   = symaddr(g_xdbc);
    float* p_delta  = symaddr(g_delta);
    float* p_y      = symaddr(g_y);

    const int M = MTOK;

    // 1) per-batch half of the gate MLP (x_stats is broadcast over L)
    hstats_kernel<<<8, 256>>>(gW1, gb1, x_stats);

    // 2) GEMM1: H = relu(X @ W1a^T + hstats[b])   (W1a = gW1[:, :512])
    sgemm_nt<128,128,8,8,1><<<dim3(D_MODEL/128, M/128), 256>>>(
        x_signal, gW1, p_h, M, D_MODEL, D_MODEL, D_MODEL, 2*D_MODEL, D_MODEL, p_hstats);

    // 3) gate scalar + residual + LayerNorm
    gate_ln_kernel<<<M, 256>>>(x_signal, x_stats, p_h, gW2, gb2, ln_g, ln_b, p_xn);

    // 4) GEMM2: XZ = XN @ in_proj_W^T   (N = 1024)
    sgemm_nt<128,128,8,8,0><<<dim3(1024/128, M/128), 256>>>(
        p_xn, in_proj_W, p_xz, M, 2*D_INNER, D_MODEL, D_MODEL, D_MODEL, 2*D_INNER, nullptr);

    // 5) causal conv (k=2) + silu -> u
    conv_silu_kernel<<<(M*D_INNER)/256, 256>>>(p_xz, conv_w, conv_b, p_u);

    // 6) GEMM3: XDBC = U @ x_proj_W^T   (N = 64)
    sgemm_nt<64,64,4,4,0><<<dim3(1, M/64), 256>>>(
        p_u, x_proj_W, p_xdbc, M, 64, D_INNER, D_INNER, D_INNER, 64, nullptr);

    // 7) GEMM4: delta = softplus(XDBC[:, :32] @ dt_proj_W^T + dt_bias)  (K = 32)
    sgemm_nt<128,128,8,8,2><<<dim3(D_INNER/128, M/128), 256>>>(
        p_xdbc, dt_proj_W, p_delta, M, D_INNER, DT_RANK, 64, DT_RANK, D_INNER, dt_proj_b);

    // 8-10) chunked selective scan
    scan_c1<<<dim3(D_INNER/128, NCHUNK, BB), 128>>>(p_xdbc, p_delta, p_u, A_log);
    scan_c2<<<16, 128>>>(A_log);
    scan_c3<<<dim3(D_INNER/128, NCHUNK, BB), 128>>>(p_xdbc, p_delta, p_u, A_log, Dp, p_xz, p_y);

    // 11) GEMM5: out = Y @ out_proj_W^T
    sgemm_nt<128,128,8,8,0><<<dim3(D_MODEL/128, M/128), 256>>>(
        p_y, out_proj_W, out, M, D_MODEL, D_INNER, D_INNER, D_INNER, D_MODEL, nullptr);
}

// round 5
// speedup vs baseline: 1.0415x; 1.0415x over previous
#include <cuda_runtime.h>
#include <math.h>

typedef unsigned long long u64;

// ---------------------------------------------------------------- constants
#define D_MODEL 512
#define D_INNER 512
#define D_STATE 16
#define DT_RANK 32
#define BB      4
#define LL      2048
#define MTOK    (BB*LL)       // 8192 tokens
#define CH_T    64            // scan chunk length
#define NCHUNK  (LL/CH_T)     // 32 chunks

// ---------------------------------------------------------------- scratch
__device__ __align__(16) float g_hstats[BB*D_MODEL];
__device__ __align__(16) float g_h    [MTOK*D_MODEL];
__device__ __align__(16) float g_xn   [MTOK*D_MODEL];
__device__ __align__(16) float g_xz   [MTOK*2*D_INNER];
__device__ __align__(16) float g_u    [MTOK*D_INNER];
__device__ __align__(16) float g_xdbc [MTOK*64];
__device__ __align__(16) float g_delta[MTOK*D_INNER];
__device__ __align__(16) float g_q    [BB*D_INNER*NCHUNK*D_STATE];
__device__ __align__(16) float g_dsum [BB*D_INNER*NCHUNK];
__device__ __align__(16) float g_hinit[BB*D_INNER*NCHUNK*D_STATE];
__device__ __align__(16) float g_y    [MTOK*D_INNER];

// ---------------------------------------------------------------- f32x2 helpers
__device__ __forceinline__ u64 pack_dup(float a) {
    u64 r;
    asm("mov.b64 %0, {%1, %1};" : "=l"(r) : "f"(a));
    return r;
}
__device__ __forceinline__ void ffma2(u64& acc, u64 a, u64 b) {
    asm("fma.rn.f32x2 %0, %1, %2, %0;" : "+l"(acc) : "l"(a), "l"(b));
}

// ---------------------------------------------------------------- SGEMM (NT)
// C[M,N] = A[M,K] @ B[N,K]^T  (both operands K-contiguous, row-major)
// EPI: 0 = none, 1 = relu(acc + bias[(m/L)*512 + n]), 2 = softplus(acc + bias[n])
// Inner loop uses packed fma.rn.f32x2 (FFMA2): 2 fp32 FMAs per issue slot.
template<int BM, int BN, int TM, int TN, int EPI>
__global__ __launch_bounds__(256)
void sgemm_nt(const float* __restrict__ A, const float* __restrict__ B,
              float* __restrict__ C, int M, int N, int K,
              int lda, int ldb, int ldc, const float* __restrict__ bias)
{
    constexpr int BK = 16;
    __shared__ float As[BK][BM + 4];
    __shared__ float Bs[BK][BN + 4];

    const int tid = threadIdx.x;
    const int tx  = tid & 15;
    const int ty  = tid >> 4;
    const int m0  = blockIdx.y * BM;
    const int n0  = blockIdx.x * BN;

    u64 acc2[TM][TN/2];
#pragma unroll
    for (int i = 0; i < TM; i++)
#pragma unroll
        for (int j = 0; j < TN/2; j++) acc2[i][j] = 0ull;

    const float* Ab = A + (size_t)m0 * lda;
    const float* Bb = B + (size_t)n0 * ldb;

    for (int k0 = 0; k0 < K; k0 += BK) {
        // load A tile (transposed into smem):   BM rows x BK cols
#pragma unroll
        for (int i = 0; i < (BM * BK) / 1024; i++) {
            int t = tid + i * 256;
            int r = t >> 2, cq = t & 3;
            float4 v = *(const float4*)(Ab + (size_t)r * lda + k0 + cq * 4);
            As[cq*4+0][r] = v.x; As[cq*4+1][r] = v.y;
            As[cq*4+2][r] = v.z; As[cq*4+3][r] = v.w;
        }
        // load B tile (transposed into smem):   BN rows x BK cols
#pragma unroll
        for (int i = 0; i < (BN * BK) / 1024; i++) {
            int t = tid + i * 256;
            int r = t >> 2, cq = t & 3;
            float4 v = *(const float4*)(Bb + (size_t)r * ldb + k0 + cq * 4);
            Bs[cq*4+0][r] = v.x; Bs[cq*4+1][r] = v.y;
            Bs[cq*4+2][r] = v.z; Bs[cq*4+3][r] = v.w;
        }
        __syncthreads();

#pragma unroll
        for (int k = 0; k < BK; k++) {
            float a[TM];
            u64   a2[TM];
            u64   b2[TN/2];
#pragma unroll
            for (int i = 0; i < TM; i += 4) {
                float4 v = *(const float4*)&As[k][ty * TM + i];
                a[i] = v.x; a[i+1] = v.y; a[i+2] = v.z; a[i+3] = v.w;
            }
#pragma unroll
            for (int j = 0; j < TN; j += 4) {
                ulonglong2 v = *(const ulonglong2*)&Bs[k][tx * TN + j];
                b2[j/2]     = v.x;
                b2[j/2 + 1] = v.y;
            }
#pragma unroll
            for (int i = 0; i < TM; i++) a2[i] = pack_dup(a[i]);
#pragma unroll
            for (int i = 0; i < TM; i++)
#pragma unroll
                for (int j = 0; j < TN/2; j++)
                    ffma2(acc2[i][j], a2[i], b2[j]);
        }
        __syncthreads();
    }

#pragma unroll
    for (int i = 0; i < TM; i++) {
        int m = m0 + ty * TM + i;
#pragma unroll
        for (int j2 = 0; j2 < TN/2; j2++) {
            int n = n0 + tx * TN + 2 * j2;
            float2 f = *(float2*)&acc2[i][j2];
            if (EPI == 1) {                 // gate MLP: + hstats[batch], relu
                const float* bb = bias + (m >> 11) * D_MODEL;   // m/2048 = batch
                f.x = fmaxf(f.x + bb[n],     0.f);
                f.y = fmaxf(f.y + bb[n + 1], 0.f);
            } else if (EPI == 2) {          // dt_proj: + bias, softplus
                f.x += bias[n];
                f.y += bias[n + 1];
                f.x = (f.x > 20.f) ? f.x : log1pf(expf(f.x));
                f.y = (f.y > 20.f) ? f.y : log1pf(expf(f.y));
            }
            *(float2*)&C[(size_t)m * ldc + n] = f;
        }
    }
}

// ---------------------------------------------------------------- hstats
// hstats[b][j] = gb1[j] + sum_k gW1[j, 512+k] * x_stats[b,k]
__global__ void hstats_kernel(const float* __restrict__ gW1,
                              const float* __restrict__ gb1,
                              const float* __restrict__ xstat)
{
    int idx = blockIdx.x * blockDim.x + threadIdx.x;
    if (idx >= BB * D_MODEL) return;
    int b = idx >> 9, j = idx & 511;
    const float* w  = gW1 + (size_t)j * (2 * D_MODEL) + D_MODEL;
    const float* xs = xstat + b * D_MODEL;
    float s = gb1[j];
#pragma unroll 8
    for (int k = 0; k < D_MODEL; k++) s = fmaf(w[k], xs[k], s);
    g_hstats[idx] = s;
}

// ---------------------------------------------------------------- gate + LN
__global__ __launch_bounds__(256)
void gate_ln_kernel(const float* __restrict__ xsig, const float* __restrict__ xstat,
                    const float* __restrict__ h,    const float* __restrict__ gW2,
                    const float* __restrict__ gb2,  const float* __restrict__ lng,
                    const float* __restrict__ lnb,  float* __restrict__ xn)
{
    const int t = blockIdx.x;          // token
    const int b = t >> 11;             // t / 2048
    const int tid = threadIdx.x;
    const int d0 = tid, d1 = tid + 256;

    __shared__ float sred[8];
    __shared__ float sred2[8][2];
    __shared__ float sbc[2];

    const float* hr = h + (size_t)t * D_MODEL;
    float p = hr[d0] * gW2[d0] + hr[d1] * gW2[d1];
#pragma unroll
    for (int o = 16; o > 0; o >>= 1) p += __shfl_xor_sync(0xffffffffu, p, o);
    if ((tid & 31) == 0) sred[tid >> 5] = p;
    __syncthreads();
    if (tid == 0) {
        float s = 0.f;
        for (int w = 0; w < 8; w++) s += sred[w];
        sbc[0] = 1.f / (1.f + expf(-(s + gb2[0])));
    }
    __syncthreads();
    const float gate = sbc[0];

    float x0 = xsig[(size_t)t * D_MODEL + d0] + gate * xstat[b * D_MODEL + d0];
    float x1 = xsig[(size_t)t * D_MODEL + d1] + gate * xstat[b * D_MODEL + d1];
    float s  = x0 + x1;
    float ss = x0 * x0 + x1 * x1;
#pragma unroll
    for (int o = 16; o > 0; o >>= 1) {
        s  += __shfl_xor_sync(0xffffffffu, s,  o);
        ss += __shfl_xor_sync(0xffffffffu, ss, o);
    }
    if ((tid & 31) == 0) { sred2[tid >> 5][0] = s; sred2[tid >> 5][1] = ss; }
    __syncthreads();
    if (tid == 0) {
        float S = 0.f, SS = 0.f;
        for (int w = 0; w < 8; w++) { S += sred2[w][0]; SS += sred2[w][1]; }
        float mu  = S * (1.f / D_MODEL);
        float var = SS * (1.f / D_MODEL) - mu * mu;
        sbc[0] = mu;
        sbc[1] = rsqrtf(var + 1e-5f);
    }
    __syncthreads();
    const float mu = sbc[0], rstd = sbc[1];
    xn[(size_t)t * D_MODEL + d0] = (x0 - mu) * rstd * lng[d0] + lnb[d0];
    xn[(size_t)t * D_MODEL + d1] = (x1 - mu) * rstd * lng[d1] + lnb[d1];
}

// ---------------------------------------------------------------- conv(k=2)+silu
__global__ void conv_silu_kernel(const float* __restrict__ xz,
                                 const float* __restrict__ conv_w,
                                 const float* __restrict__ conv_b,
                                 float* __restrict__ u)
{
    int idx = blockIdx.x * blockDim.x + threadIdx.x;
    if (idx >= MTOK * D_INNER) return;
    int d = idx & 511;
    int l = (idx >> 9) & (LL - 1);
    int t = idx >> 9;                                  // b*L + l
    float ucur  = xz[(size_t)t * (2 * D_INNER) + d];
    float uprev = (l > 0) ? xz[(size_t)(t - 1) * (2 * D_INNER) + d] : 0.f;
    float v = conv_b[d] + conv_w[d * 2 + 0] * uprev + conv_w[d * 2 + 1] * ucur;
    float sg = 1.f / (1.f + __expf(-v));
    u[idx] = v * sg;
}

// ---------------------------------------------------------------- scan helpers
__device__ __forceinline__ bool load_aexp(const float* __restrict__ A_log,
                                          int d, float* aexp)
{
    bool fast = true;
#pragma unroll
    for (int n = 0; n < D_STATE; n++) {
        aexp[n] = expf(A_log[d * D_STATE + n]);        // = -A[d,n]
        if (fabsf(aexp[n] - (float)(n + 1)) > 1e-2f) fast = false;
    }
    return fast;
}

// ---- pass 1: per-chunk local scan (h starts at 0) -> q[16], sum(delta)
__global__ __launch_bounds__(128)
void scan_c1(const float* __restrict__ xdbc, const float* __restrict__ delta,
             const float* __restrict__ u,    const float* __restrict__ A_log)
{
    const int d = blockIdx.x * 128 + threadIdx.x;
    const int c = blockIdx.y, b = blockIdx.z;

    __shared__ float sB[CH_T * D_STATE];
    for (int i = threadIdx.x; i < CH_T * D_STATE; i += 128) {
        int j = i >> 4, n = i & 15;
        sB[i] = xdbc[(size_t)(b * LL + c * CH_T + j) * 64 + DT_RANK + n];
    }
    __syncthreads();

    float aexp[D_STATE];
    const bool fast = load_aexp(A_log, d, aexp);

    float h[D_STATE];
#pragma unroll
    for (int n = 0; n < D_STATE; n++) h[n] = 0.f;
    float dsum = 0.f;

    const float* dp = delta + (size_t)(b * LL + c * CH_T) * D_INNER + d;
    const float* up = u     + (size_t)(b * LL + c * CH_T) * D_INNER + d;

    if (fast) {
        for (int j = 0; j < CH_T; j++) {
            float de = dp[j * D_INNER], uu = up[j * D_INNER];
            dsum += de;
            float du = de * uu;
            float r = __expf(-de), rp = r;
#pragma unroll
            for (int n = 0; n < D_STATE; n++) {
                h[n] = fmaf(rp, h[n], du * sB[j * D_STATE + n]);
                rp *= r;
            }
        }
    } else {
        for (int j = 0; j < CH_T; j++) {
            float de = dp[j * D_INNER], uu = up[j * D_INNER];
            dsum += de;
            float du = de * uu;
#pragma unroll
            for (int n = 0; n < D_STATE; n++)
                h[n] = fmaf(__expf(-de * aexp[n]), h[n], du * sB[j * D_STATE + n]);
        }
    }

    const size_t base = (size_t)(b * D_INNER + d) * NCHUNK + c;
#pragma unroll
    for (int n = 0; n < D_STATE; n++) g_q[base * D_STATE + n] = h[n];
    g_dsum[base] = dsum;
}

// ---- pass 2: cross-chunk scan (per (b,d)) -> hinit per chunk
__global__ void scan_c2(const float* __restrict__ A_log)
{
    int bd = blockIdx.x * blockDim.x + threadIdx.x;
    if (bd >= BB * D_INNER) return;
    int d = bd & 511;

    float aexp[D_STATE];
    const bool fast = load_aexp(A_log, d, aexp);

    float h[D_STATE];
#pragma unroll
    for (int n = 0; n < D_STATE; n++) h[n] = 0.f;

    for (int c = 0; c < NCHUNK; c++) {
        const size_t base = (size_t)bd * NCHUNK + c;
#pragma unroll
        for (int n = 0; n < D_STATE; n++) g_hinit[base * D_STATE + n] = h[n];
        float ds = g_dsum[base];
        if (fast) {
            float r = __expf(-ds), rp = r;
#pragma unroll
            for (int n = 0; n < D_STATE; n++) {
                h[n] = fmaf(rp, h[n], g_q[base * D_STATE + n]);
                rp *= r;
            }
        } else {
#pragma unroll
            for (int n = 0; n < D_STATE; n++)
                h[n] = fmaf(__expf(-ds * aexp[n]), h[n], g_q[base * D_STATE + n]);
        }
    }
}

// ---- pass 3: per-chunk replay with correct init; y = <h,C>, fused epilogue
__global__ __launch_bounds__(128)
void scan_c3(const float* __restrict__ xdbc, const float* __restrict__ delta,
             const float* __restrict__ u,    const float* __restrict__ A_log,
             const float* __restrict__ Dp,   const float* __restrict__ xz,
             float* __restrict__ y)
{
    const int d = blockIdx.x * 128 + threadIdx.x;
    const int c = blockIdx.y, b = blockIdx.z;

    __shared__ float sB[CH_T * D_STATE];
    __shared__ float sC[CH_T * D_STATE];
    for (int i = threadIdx.x; i < CH_T * D_STATE; i += 128) {
        int j = i >> 4, n = i & 15;
        const float* row = xdbc + (size_t)(b * LL + c * CH_T + j) * 64;
        sB[i] = row[DT_RANK + n];
        sC[i] = row[DT_RANK + D_STATE + n];
    }
    __syncthreads();

    float aexp[D_STATE];
    const bool fast = load_aexp(A_log, d, aexp);

    const size_t base = (size_t)(b * D_INNER + d) * NCHUNK + c;
    float h[D_STATE];
#pragma unroll
    for (int n = 0; n < D_STATE; n++) h[n] = g_hinit[base * D_STATE + n];

    const float dpd = Dp[d];
    const float* dptr = delta + (size_t)(b * LL + c * CH_T) * D_INNER + d;
    const float* uptr = u     + (size_t)(b * LL + c * CH_T) * D_INNER + d;

    for (int j = 0; j < CH_T; j++) {
        float de = dptr[j * D_INNER], uu = uptr[j * D_INNER];
        float du = de * uu;
        float yv = 0.f;
        if (fast) {
            float r = __expf(-de), rp = r;
#pragma unroll
            for (int n = 0; n < D_STATE; n++) {
                h[n] = fmaf(rp, h[n], du * sB[j * D_STATE + n]);
                yv   = fmaf(h[n], sC[j * D_STATE + n], yv);
                rp *= r;
            }
        } else {
#pragma unroll
            for (int n = 0; n < D_STATE; n++) {
                h[n] = fmaf(__expf(-de * aexp[n]), h[n], du * sB[j * D_STATE + n]);
                yv   = fmaf(h[n], sC[j * D_STATE + n], yv);
            }
        }
        const int l = b * LL + c * CH_T + j;
        float z  = xz[(size_t)l * (2 * D_INNER) + D_INNER + d];
        float sg = 1.f / (1.f + __expf(-z));
        y[(size_t)l * D_INNER + d] = (yv + dpd * uu) * (z * sg);
    }
}

// ---------------------------------------------------------------- launch
static float* symaddr(const void* sym)
{
    void* p = nullptr;
    cudaGetSymbolAddress(&p, sym);
    return (float*)p;
}

extern "C" void kernel_launch(void* const* d_in, const int* in_sizes, int n_in,
                              void* d_out, int out_size)
{
    const float* x_signal  = (const float*)d_in[0];
    const float* x_stats   = (const float*)d_in[1];
    const float* gW1       = (const float*)d_in[2];
    const float* gb1       = (const float*)d_in[3];
    const float* gW2       = (const float*)d_in[4];
    const float* gb2       = (const float*)d_in[5];
    const float* ln_g      = (const float*)d_in[6];
    const float* ln_b      = (const float*)d_in[7];
    const float* in_proj_W = (const float*)d_in[8];
    const float* conv_w    = (const float*)d_in[9];
    const float* conv_b    = (const float*)d_in[10];
    const float* x_proj_W  = (const float*)d_in[11];
    const float* dt_proj_W = (const float*)d_in[12];
    const float* dt_proj_b = (const float*)d_in[13];
    const float* A_log     = (const float*)d_in[14];
    const float* Dp        = (const float*)d_in[15];
    const float* out_proj_W= (const float*)d_in[16];
    float* out = (float*)d_out;

    float* p_hstats = symaddr(g_hstats);
    float* p_h      = symaddr(g_h);
    float* p_xn     = symaddr(g_xn);
    float* p_xz     = symaddr(g_xz);
    float* p_u      = symaddr(g_u);
    float* p_xdbc   = symaddr(g_xdbc);
    float* p_delta  = symaddr(g_delta);
    float* p_y      = symaddr(g_y);

    const int M = MTOK;

    // 1) per-batch half of the gate MLP (x_stats is broadcast over L)
    hstats_kernel<<<8, 256>>>(gW1, gb1, x_stats);

    // 2) GEMM1: H = relu(X @ W1a^T + hstats[b])   (W1a = gW1[:, :512])
    sgemm_nt<128,128,8,8,1><<<dim3(D_MODEL/128, M/128), 256>>>(
        x_signal, gW1, p_h, M, D_MODEL, D_MODEL, D_MODEL, 2*D_MODEL, D_MODEL, p_hstats);

    // 3) gate scalar + residual + LayerNorm
    gate_ln_kernel<<<M, 256>>>(x_signal, x_stats, p_h, gW2, gb2, ln_g, ln_b, p_xn);

    // 4) GEMM2: XZ = XN @ in_proj_W^T   (N = 1024)
    sgemm_nt<128,128,8,8,0><<<dim3(1024/128, M/128), 256>>>(
        p_xn, in_proj_W, p_xz, M, 2*D_INNER, D_MODEL, D_MODEL, D_MODEL, 2*D_INNER, nullptr);

    // 5) causal conv (k=2) + silu -> u
    conv_silu_kernel<<<(M*D_INNER)/256, 256>>>(p_xz, conv_w, conv_b, p_u);

    // 6) GEMM3: XDBC = U @ x_proj_W^T   (N = 64)
    sgemm_nt<64,64,4,4,0><<<dim3(1, M/64), 256>>>(
        p_u, x_proj_W, p_xdbc, M, 64, D_INNER, D_INNER, D_INNER, 64, nullptr);

    // 7) GEMM4: delta = softplus(XDBC[:, :32] @ dt_proj_W^T + dt_bias)  (K = 32)
    sgemm_nt<128,128,8,8,2><<<dim3(D_INNER/128, M/128), 256>>>(
        p_xdbc, dt_proj_W, p_delta, M, D_INNER, DT_RANK, 64, DT_RANK, D_INNER, dt_proj_b);

    // 8-10) chunked selective scan
    scan_c1<<<dim3(D_INNER/128, NCHUNK, BB), 128>>>(p_xdbc, p_delta, p_u, A_log);
    scan_c2<<<16, 128>>>(A_log);
    scan_c3<<<dim3(D_INNER/128, NCHUNK, BB), 128>>>(p_xdbc, p_delta, p_u, A_log, Dp, p_xz, p_y);

    // 11) GEMM5: out = Y @ out_proj_W^T
    sgemm_nt<128,128,8,8,0><<<dim3(D_MODEL/128, M/128), 256>>>(
        p_y, out_proj_W, out, M, D_MODEL, D_INNER, D_INNER, D_INNER, D_MODEL, nullptr);
}

// round 6
// speedup vs baseline: 1.7711x; 1.7006x over previous
#include <cuda_runtime.h>
#include <math.h>

typedef unsigned long long u64;
typedef unsigned int u32;

// ---------------------------------------------------------------- constants
#define D_MODEL 512
#define D_INNER 512
#define D_STATE 16
#define DT_RANK 32
#define BB      4
#define LL      2048
#define MTOK    (BB*LL)       // 8192 tokens
#define CH_T    64            // scan chunk length
#define NCHUNK  (LL/CH_T)     // 32 chunks

// ---------------------------------------------------------------- scratch
__device__ __align__(16) float g_hstats[BB*D_MODEL];
__device__ __align__(16) float g_h    [MTOK*D_MODEL];
__device__ __align__(16) float g_xn   [MTOK*D_MODEL];
__device__ __align__(16) float g_xz   [MTOK*2*D_INNER];
__device__ __align__(16) float g_u    [MTOK*D_INNER];
__device__ __align__(16) float g_xdbc [MTOK*64];
__device__ __align__(16) float g_delta[MTOK*D_INNER];
__device__ __align__(16) float g_q    [BB*D_INNER*NCHUNK*D_STATE];
__device__ __align__(16) float g_dsum [BB*D_INNER*NCHUNK];
__device__ __align__(16) float g_hinit[BB*D_INNER*NCHUNK*D_STATE];
__device__ __align__(16) float g_y    [MTOK*D_INNER];

// ---------------------------------------------------------------- tf32 helpers
__device__ __forceinline__ u32 f2tf32(float f) {
    u32 r;
    asm("cvt.rna.tf32.f32 %0, %1;" : "=r"(r) : "f"(f));
    return r;
}
__device__ __forceinline__ void mma_tf32(float* d, const u32* a, const u32* b) {
    asm volatile(
        "mma.sync.aligned.m16n8k8.row.col.f32.tf32.tf32.f32 "
        "{%0,%1,%2,%3}, {%4,%5,%6,%7}, {%8,%9}, {%0,%1,%2,%3};"
        : "+f"(d[0]), "+f"(d[1]), "+f"(d[2]), "+f"(d[3])
        : "r"(a[0]), "r"(a[1]), "r"(a[2]), "r"(a[3]), "r"(b[0]), "r"(b[1]));
}

// ---------------------------------------------------------------- TF32 GEMM (NT)
// C[M,N] = A[M,K] @ B[N,K]^T ; tf32 inputs, fp32 accumulate.
// Block 128x128, BK=32, 256 threads = 8 warps (4 M x 2 N), warp tile 32x64.
// EPI: 0 = none, 1 = relu(acc + bias[(m>>11)*512 + n])
template<int EPI>
__global__ __launch_bounds__(256)
void tf32gemm_nt(const float* __restrict__ A, const float* __restrict__ B,
                 float* __restrict__ C, int M, int N, int K,
                 int lda, int ldb, int ldc, const float* __restrict__ bias)
{
    constexpr int BM = 128, BN = 128, BK = 32, LDS_S = BK + 4;  // 36: (4g+t)%32 unique
    __shared__ u32 As[BM][LDS_S];
    __shared__ u32 Bs[BN][LDS_S];

    const int tid  = threadIdx.x;
    const int lane = tid & 31;
    const int warp = tid >> 5;
    const int gid  = lane >> 2;      // 0..7
    const int tig  = lane & 3;       // 0..3
    const int wm   = warp & 3;       // 4 warps along M
    const int wn   = warp >> 2;      // 2 warps along N
    const int m0   = blockIdx.y * BM;
    const int n0   = blockIdx.x * BN;

    float acc[2][8][4];
#pragma unroll
    for (int i = 0; i < 2; i++)
#pragma unroll
        for (int j = 0; j < 8; j++)
#pragma unroll
            for (int r = 0; r < 4; r++) acc[i][j][r] = 0.f;

    // tile loader: 128 rows x 32 cols; 8 float4-chunks/row; 32 rows per pass
    const int lr = tid >> 3;         // row within pass
    const int lc = (tid & 7) * 4;    // k offset

    for (int k0 = 0; k0 < K; k0 += BK) {
#pragma unroll
        for (int p = 0; p < 4; p++) {
            int r = lr + p * 32;
            float4 va = *(const float4*)(A + (size_t)(m0 + r) * lda + k0 + lc);
            As[r][lc + 0] = f2tf32(va.x); As[r][lc + 1] = f2tf32(va.y);
            As[r][lc + 2] = f2tf32(va.z); As[r][lc + 3] = f2tf32(va.w);
            float4 vb = *(const float4*)(B + (size_t)(n0 + r) * ldb + k0 + lc);
            Bs[r][lc + 0] = f2tf32(vb.x); Bs[r][lc + 1] = f2tf32(vb.y);
            Bs[r][lc + 2] = f2tf32(vb.z); Bs[r][lc + 3] = f2tf32(vb.w);
        }
        __syncthreads();

#pragma unroll
        for (int ka = 0; ka < 4; ka++) {
            const int kk = ka * 8;
            u32 af[2][4];
#pragma unroll
            for (int i = 0; i < 2; i++) {
                const int mr = wm * 32 + i * 16;
                af[i][0] = As[mr + gid    ][kk + tig    ];
                af[i][1] = As[mr + gid + 8][kk + tig    ];
                af[i][2] = As[mr + gid    ][kk + tig + 4];
                af[i][3] = As[mr + gid + 8][kk + tig + 4];
            }
            u32 bf[8][2];
#pragma unroll
            for (int j = 0; j < 8; j++) {
                const int nr = wn * 64 + j * 8;
                bf[j][0] = Bs[nr + gid][kk + tig    ];
                bf[j][1] = Bs[nr + gid][kk + tig + 4];
            }
#pragma unroll
            for (int i = 0; i < 2; i++)
#pragma unroll
                for (int j = 0; j < 8; j++)
                    mma_tf32(acc[i][j], af[i], bf[j]);
        }
        __syncthreads();
    }

    // epilogue: c0=(gid, 2t), c1=(gid, 2t+1), c2=(gid+8, 2t), c3=(gid+8, 2t+1)
#pragma unroll
    for (int i = 0; i < 2; i++) {
        const int mlo = m0 + wm * 32 + i * 16 + gid;
        const int mhi = mlo + 8;
#pragma unroll
        for (int j = 0; j < 8; j++) {
            const int n = n0 + wn * 64 + j * 8 + tig * 2;
            float2 f01 = make_float2(acc[i][j][0], acc[i][j][1]);
            float2 f23 = make_float2(acc[i][j][2], acc[i][j][3]);
            if (EPI == 1) {
                const float* blo = bias + (mlo >> 11) * D_MODEL;
                const float* bhi = bias + (mhi >> 11) * D_MODEL;
                f01.x = fmaxf(f01.x + blo[n], 0.f); f01.y = fmaxf(f01.y + blo[n + 1], 0.f);
                f23.x = fmaxf(f23.x + bhi[n], 0.f); f23.y = fmaxf(f23.y + bhi[n + 1], 0.f);
            }
            *(float2*)&C[(size_t)mlo * ldc + n] = f01;
            *(float2*)&C[(size_t)mhi * ldc + n] = f23;
        }
    }
}

// ---------------------------------------------------------------- fp32 SGEMM (NT) for small GEMMs
template<int BM, int BN, int TM, int TN, int EPI>
__global__ __launch_bounds__(256)
void sgemm_nt(const float* __restrict__ A, const float* __restrict__ B,
              float* __restrict__ C, int M, int N, int K,
              int lda, int ldb, int ldc, const float* __restrict__ bias)
{
    constexpr int BK = 16;
    __shared__ float As[BK][BM + 4];
    __shared__ float Bs[BK][BN + 4];

    const int tid = threadIdx.x;
    const int tx  = tid & 15;
    const int ty  = tid >> 4;
    const int m0  = blockIdx.y * BM;
    const int n0  = blockIdx.x * BN;

    float acc[TM][TN];
#pragma unroll
    for (int i = 0; i < TM; i++)
#pragma unroll
        for (int j = 0; j < TN; j++) acc[i][j] = 0.f;

    const float* Ab = A + (size_t)m0 * lda;
    const float* Bb = B + (size_t)n0 * ldb;

    for (int k0 = 0; k0 < K; k0 += BK) {
#pragma unroll
        for (int i = 0; i < (BM * BK) / 1024; i++) {
            int t = tid + i * 256;
            int r = t >> 2, cq = t & 3;
            float4 v = *(const float4*)(Ab + (size_t)r * lda + k0 + cq * 4);
            As[cq*4+0][r] = v.x; As[cq*4+1][r] = v.y;
            As[cq*4+2][r] = v.z; As[cq*4+3][r] = v.w;
        }
#pragma unroll
        for (int i = 0; i < (BN * BK) / 1024; i++) {
            int t = tid + i * 256;
            int r = t >> 2, cq = t & 3;
            float4 v = *(const float4*)(Bb + (size_t)r * ldb + k0 + cq * 4);
            Bs[cq*4+0][r] = v.x; Bs[cq*4+1][r] = v.y;
            Bs[cq*4+2][r] = v.z; Bs[cq*4+3][r] = v.w;
        }
        __syncthreads();

#pragma unroll
        for (int k = 0; k < BK; k++) {
            float a[TM], b[TN];
#pragma unroll
            for (int i = 0; i < TM; i += 4) {
                float4 v = *(const float4*)&As[k][ty * TM + i];
                a[i] = v.x; a[i+1] = v.y; a[i+2] = v.z; a[i+3] = v.w;
            }
#pragma unroll
            for (int j = 0; j < TN; j += 4) {
                float4 v = *(const float4*)&Bs[k][tx * TN + j];
                b[j] = v.x; b[j+1] = v.y; b[j+2] = v.z; b[j+3] = v.w;
            }
#pragma unroll
            for (int i = 0; i < TM; i++)
#pragma unroll
                for (int j = 0; j < TN; j++)
                    acc[i][j] = fmaf(a[i], b[j], acc[i][j]);
        }
        __syncthreads();
    }

#pragma unroll
    for (int i = 0; i < TM; i++) {
        int m = m0 + ty * TM + i;
#pragma unroll
        for (int j = 0; j < TN; j++) {
            int n = n0 + tx * TN + j;
            float v = acc[i][j];
            if (EPI == 2) {          // dt_proj: + bias, softplus
                v += bias[n];
                v = (v > 20.f) ? v : log1pf(expf(v));
            }
            C[(size_t)m * ldc + n] = v;
        }
    }
}

// ---------------------------------------------------------------- hstats
__global__ void hstats_kernel(const float* __restrict__ gW1,
                              const float* __restrict__ gb1,
                              const float* __restrict__ xstat)
{
    int idx = blockIdx.x * blockDim.x + threadIdx.x;
    if (idx >= BB * D_MODEL) return;
    int b = idx >> 9, j = idx & 511;
    const float* w  = gW1 + (size_t)j * (2 * D_MODEL) + D_MODEL;
    const float* xs = xstat + b * D_MODEL;
    float s = gb1[j];
#pragma unroll 8
    for (int k = 0; k < D_MODEL; k++) s = fmaf(w[k], xs[k], s);
    g_hstats[idx] = s;
}

// ---------------------------------------------------------------- gate + LN
__global__ __launch_bounds__(256)
void gate_ln_kernel(const float* __restrict__ xsig, const float* __restrict__ xstat,
                    const float* __restrict__ h,    const float* __restrict__ gW2,
                    const float* __restrict__ gb2,  const float* __restrict__ lng,
                    const float* __restrict__ lnb,  float* __restrict__ xn)
{
    const int t = blockIdx.x;
    const int b = t >> 11;
    const int tid = threadIdx.x;
    const int d0 = tid, d1 = tid + 256;

    __shared__ float sred[8];
    __shared__ float sred2[8][2];
    __shared__ float sbc[2];

    const float* hr = h + (size_t)t * D_MODEL;
    float p = hr[d0] * gW2[d0] + hr[d1] * gW2[d1];
#pragma unroll
    for (int o = 16; o > 0; o >>= 1) p += __shfl_xor_sync(0xffffffffu, p, o);
    if ((tid & 31) == 0) sred[tid >> 5] = p;
    __syncthreads();
    if (tid == 0) {
        float s = 0.f;
        for (int w = 0; w < 8; w++) s += sred[w];
        sbc[0] = 1.f / (1.f + expf(-(s + gb2[0])));
    }
    __syncthreads();
    const float gate = sbc[0];

    float x0 = xsig[(size_t)t * D_MODEL + d0] + gate * xstat[b * D_MODEL + d0];
    float x1 = xsig[(size_t)t * D_MODEL + d1] + gate * xstat[b * D_MODEL + d1];
    float s  = x0 + x1;
    float ss = x0 * x0 + x1 * x1;
#pragma unroll
    for (int o = 16; o > 0; o >>= 1) {
        s  += __shfl_xor_sync(0xffffffffu, s,  o);
        ss += __shfl_xor_sync(0xffffffffu, ss, o);
    }
    if ((tid & 31) == 0) { sred2[tid >> 5][0] = s; sred2[tid >> 5][1] = ss; }
    __syncthreads();
    if (tid == 0) {
        float S = 0.f, SS = 0.f;
        for (int w = 0; w < 8; w++) { S += sred2[w][0]; SS += sred2[w][1]; }
        float mu  = S * (1.f / D_MODEL);
        float var = SS * (1.f / D_MODEL) - mu * mu;
        sbc[0] = mu;
        sbc[1] = rsqrtf(var + 1e-5f);
    }
    __syncthreads();
    const float mu = sbc[0], rstd = sbc[1];
    xn[(size_t)t * D_MODEL + d0] = (x0 - mu) * rstd * lng[d0] + lnb[d0];
    xn[(size_t)t * D_MODEL + d1] = (x1 - mu) * rstd * lng[d1] + lnb[d1];
}

// ---------------------------------------------------------------- conv(k=2)+silu
__global__ void conv_silu_kernel(const float* __restrict__ xz,
                                 const float* __restrict__ conv_w,
                                 const float* __restrict__ conv_b,
                                 float* __restrict__ u)
{
    int idx = blockIdx.x * blockDim.x + threadIdx.x;
    if (idx >= MTOK * D_INNER) return;
    int d = idx & 511;
    int l = (idx >> 9) & (LL - 1);
    int t = idx >> 9;
    float ucur  = xz[(size_t)t * (2 * D_INNER) + d];
    float uprev = (l > 0) ? xz[(size_t)(t - 1) * (2 * D_INNER) + d] : 0.f;
    float v = conv_b[d] + conv_w[d * 2 + 0] * uprev + conv_w[d * 2 + 1] * ucur;
    float sg = 1.f / (1.f + __expf(-v));
    u[idx] = v * sg;
}

// ---------------------------------------------------------------- scan helpers
__device__ __forceinline__ bool load_aexp(const float* __restrict__ A_log,
                                          int d, float* aexp)
{
    bool fast = true;
#pragma unroll
    for (int n = 0; n < D_STATE; n++) {
        aexp[n] = expf(A_log[d * D_STATE + n]);
        if (fabsf(aexp[n] - (float)(n + 1)) > 1e-2f) fast = false;
    }
    return fast;
}

// ---- pass 1
__global__ __launch_bounds__(128)
void scan_c1(const float* __restrict__ xdbc, const float* __restrict__ delta,
             const float* __restrict__ u,    const float* __restrict__ A_log)
{
    const int d = blockIdx.x * 128 + threadIdx.x;
    const int c = blockIdx.y, b = blockIdx.z;

    __shared__ float sB[CH_T * D_STATE];
    for (int i = threadIdx.x; i < CH_T * D_STATE; i += 128) {
        int j = i >> 4, n = i & 15;
        sB[i] = xdbc[(size_t)(b * LL + c * CH_T + j) * 64 + DT_RANK + n];
    }
    __syncthreads();

    float aexp[D_STATE];
    const bool fast = load_aexp(A_log, d, aexp);

    float h[D_STATE];
#pragma unroll
    for (int n = 0; n < D_STATE; n++) h[n] = 0.f;
    float dsum = 0.f;

    const float* dp = delta + (size_t)(b * LL + c * CH_T) * D_INNER + d;
    const float* up = u     + (size_t)(b * LL + c * CH_T) * D_INNER + d;

    if (fast) {
        for (int j = 0; j < CH_T; j++) {
            float de = dp[j * D_INNER], uu = up[j * D_INNER];
            dsum += de;
            float du = de * uu;
            float r = __expf(-de), rp = r;
#pragma unroll
            for (int n = 0; n < D_STATE; n++) {
                h[n] = fmaf(rp, h[n], du * sB[j * D_STATE + n]);
                rp *= r;
            }
        }
    } else {
        for (int j = 0; j < CH_T; j++) {
            float de = dp[j * D_INNER], uu = up[j * D_INNER];
            dsum += de;
            float du = de * uu;
#pragma unroll
            for (int n = 0; n < D_STATE; n++)
                h[n] = fmaf(__expf(-de * aexp[n]), h[n], du * sB[j * D_STATE + n]);
        }
    }

    const size_t base = (size_t)(b * D_INNER + d) * NCHUNK + c;
#pragma unroll
    for (int n = 0; n < D_STATE; n++) g_q[base * D_STATE + n] = h[n];
    g_dsum[base] = dsum;
}

// ---- pass 2
__global__ void scan_c2(const float* __restrict__ A_log)
{
    int bd = blockIdx.x * blockDim.x + threadIdx.x;
    if (bd >= BB * D_INNER) return;
    int d = bd & 511;

    float aexp[D_STATE];
    const bool fast = load_aexp(A_log, d, aexp);

    float h[D_STATE];
#pragma unroll
    for (int n = 0; n < D_STATE; n++) h[n] = 0.f;

    for (int c = 0; c < NCHUNK; c++) {
        const size_t base = (size_t)bd * NCHUNK + c;
#pragma unroll
        for (int n = 0; n < D_STATE; n++) g_hinit[base * D_STATE + n] = h[n];
        float ds = g_dsum[base];
        if (fast) {
            float r = __expf(-ds), rp = r;
#pragma unroll
            for (int n = 0; n < D_STATE; n++) {
                h[n] = fmaf(rp, h[n], g_q[base * D_STATE + n]);
                rp *= r;
            }
        } else {
#pragma unroll
            for (int n = 0; n < D_STATE; n++)
                h[n] = fmaf(__expf(-ds * aexp[n]), h[n], g_q[base * D_STATE + n]);
        }
    }
}

// ---- pass 3
__global__ __launch_bounds__(128)
void scan_c3(const float* __restrict__ xdbc, const float* __restrict__ delta,
             const float* __restrict__ u,    const float* __restrict__ A_log,
             const float* __restrict__ Dp,   const float* __restrict__ xz,
             float* __restrict__ y)
{
    const int d = blockIdx.x * 128 + threadIdx.x;
    const int c = blockIdx.y, b = blockIdx.z;

    __shared__ float sB[CH_T * D_STATE];
    __shared__ float sC[CH_T * D_STATE];
    for (int i = threadIdx.x; i < CH_T * D_STATE; i += 128) {
        int j = i >> 4, n = i & 15;
        const float* row = xdbc + (size_t)(b * LL + c * CH_T + j) * 64;
        sB[i] = row[DT_RANK + n];
        sC[i] = row[DT_RANK + D_STATE + n];
    }
    __syncthreads();

    float aexp[D_STATE];
    const bool fast = load_aexp(A_log, d, aexp);

    const size_t base = (size_t)(b * D_INNER + d) * NCHUNK + c;
    float h[D_STATE];
#pragma unroll
    for (int n = 0; n < D_STATE; n++) h[n] = g_hinit[base * D_STATE + n];

    const float dpd = Dp[d];
    const float* dptr = delta + (size_t)(b * LL + c * CH_T) * D_INNER + d;
    const float* uptr = u     + (size_t)(b * LL + c * CH_T) * D_INNER + d;

    for (int j = 0; j < CH_T; j++) {
        float de = dptr[j * D_INNER], uu = uptr[j * D_INNER];
        float du = de * uu;
        float yv = 0.f;
        if (fast) {
            float r = __expf(-de), rp = r;
#pragma unroll
            for (int n = 0; n < D_STATE; n++) {
                h[n] = fmaf(rp, h[n], du * sB[j * D_STATE + n]);
                yv   = fmaf(h[n], sC[j * D_STATE + n], yv);
                rp *= r;
            }
        } else {
#pragma unroll
            for (int n = 0; n < D_STATE; n++) {
                h[n] = fmaf(__expf(-de * aexp[n]), h[n], du * sB[j * D_STATE + n]);
                yv   = fmaf(h[n], sC[j * D_STATE + n], yv);
            }
        }
        const int l = b * LL + c * CH_T + j;
        float z  = xz[(size_t)l * (2 * D_INNER) + D_INNER + d];
        float sg = 1.f / (1.f + __expf(-z));
        y[(size_t)l * D_INNER + d] = (yv + dpd * uu) * (z * sg);
    }
}

// ---------------------------------------------------------------- launch
static float* symaddr(const void* sym)
{
    void* p = nullptr;
    cudaGetSymbolAddress(&p, sym);
    return (float*)p;
}

extern "C" void kernel_launch(void* const* d_in, const int* in_sizes, int n_in,
                              void* d_out, int out_size)
{
    const float* x_signal  = (const float*)d_in[0];
    const float* x_stats   = (const float*)d_in[1];
    const float* gW1       = (const float*)d_in[2];
    const float* gb1       = (const float*)d_in[3];
    const float* gW2       = (const float*)d_in[4];
    const float* gb2       = (const float*)d_in[5];
    const float* ln_g      = (const float*)d_in[6];
    const float* ln_b      = (const float*)d_in[7];
    const float* in_proj_W = (const float*)d_in[8];
    const float* conv_w    = (const float*)d_in[9];
    const float* conv_b    = (const float*)d_in[10];
    const float* x_proj_W  = (const float*)d_in[11];
    const float* dt_proj_W = (const float*)d_in[12];
    const float* dt_proj_b = (const float*)d_in[13];
    const float* A_log     = (const float*)d_in[14];
    const float* Dp        = (const float*)d_in[15];
    const float* out_proj_W= (const float*)d_in[16];
    float* out = (float*)d_out;

    float* p_hstats = symaddr(g_hstats);
    float* p_h      = symaddr(g_h);
    float* p_xn     = symaddr(g_xn);
    float* p_xz     = symaddr(g_xz);
    float* p_u      = symaddr(g_u);
    float* p_xdbc   = symaddr(g_xdbc);
    float* p_delta  = symaddr(g_delta);
    float* p_y      = symaddr(g_y);

    const int M = MTOK;

    // 1) per-batch half of the gate MLP (x_stats is broadcast over L)
    hstats_kernel<<<8, 256>>>(gW1, gb1, x_stats);

    // 2) GEMM1 (tf32): H = relu(X @ W1a^T + hstats[b])
    tf32gemm_nt<1><<<dim3(D_MODEL/128, M/128), 256>>>(
        x_signal, gW1, p_h, M, D_MODEL, D_MODEL, D_MODEL, 2*D_MODEL, D_MODEL, p_hstats);

    // 3) gate scalar + residual + LayerNorm
    gate_ln_kernel<<<M, 256>>>(x_signal, x_stats, p_h, gW2, gb2, ln_g, ln_b, p_xn);

    // 4) GEMM2 (tf32): XZ = XN @ in_proj_W^T   (N = 1024)
    tf32gemm_nt<0><<<dim3(1024/128, M/128), 256>>>(
        p_xn, in_proj_W, p_xz, M, 2*D_INNER, D_MODEL, D_MODEL, D_MODEL, 2*D_INNER, nullptr);

    // 5) causal conv (k=2) + silu -> u
    conv_silu_kernel<<<(M*D_INNER)/256, 256>>>(p_xz, conv_w, conv_b, p_u);

    // 6) GEMM3 (fp32): XDBC = U @ x_proj_W^T   (N = 64)
    sgemm_nt<64,64,4,4,0><<<dim3(1, M/64), 256>>>(
        p_u, x_proj_W, p_xdbc, M, 64, D_INNER, D_INNER, D_INNER, 64, nullptr);

    // 7) GEMM4 (fp32): delta = softplus(XDBC[:, :32] @ dt_proj_W^T + dt_bias)
    sgemm_nt<128,128,8,8,2><<<dim3(D_INNER/128, M/128), 256>>>(
        p_xdbc, dt_proj_W, p_delta, M, D_INNER, DT_RANK, 64, DT_RANK, D_INNER, dt_proj_b);

    // 8-10) chunked selective scan
    scan_c1<<<dim3(D_INNER/128, NCHUNK, BB), 128>>>(p_xdbc, p_delta, p_u, A_log);
    scan_c2<<<16, 128>>>(A_log);
    scan_c3<<<dim3(D_INNER/128, NCHUNK, BB), 128>>>(p_xdbc, p_delta, p_u, A_log, Dp, p_xz, p_y);

    // 11) GEMM5 (tf32): out = Y @ out_proj_W^T
    tf32gemm_nt<0><<<dim3(D_MODEL/128, M/128), 256>>>(
        p_y, out_proj_W, out, M, D_MODEL, D_INNER, D_INNER, D_INNER, D_MODEL, nullptr);
}